// round 3
// baseline (speedup 1.0000x reference)
#include <cuda_runtime.h>

// Problem constants
#define B_   8
#define F_   32      // input channels
#define NN   256     // nodes
#define MM   64
#define CO   64      // output channels
#define CC   224     // concat channels = 7*32
#define KP   32      // K-panel rows for A streaming

// SMEM layout (floats):
//   Xs  [32*256]  : X tile (left operand, persistent)
//   X1s [32*256]  : X1 / X2 tile
//   As  [KP*256]  : A panel
// total = 3 * 8192 floats = 96 KB dynamic smem

__device__ __forceinline__ void nconv_step(
    const float* __restrict__ Ag,   // A[b][m] base: [256][256] contiguous
    const float* Xsrc,              // smem [32][256]
    float*       Xdst,              // smem [32][256] (may alias Xsrc)
    float*       As,                // smem panel [KP][256]
    int tx, int ty, int t)
{
    float acc0[16], acc1[16];
#pragma unroll
    for (int c = 0; c < 16; ++c) { acc0[c] = 0.f; acc1[c] = 0.f; }

    for (int kp = 0; kp < NN / KP; ++kp) {
        __syncthreads();
        // Panel is a contiguous 8192-float block of A (row stride 256 matches)
        const float4* src4 = (const float4*)(Ag + kp * KP * NN);
        float4* dst4 = (float4*)As;
#pragma unroll
        for (int i = 0; i < (KP * NN / 4) / 256; ++i)   // 8 float4 per thread
            dst4[t + 256 * i] = src4[t + 256 * i];
        __syncthreads();

#pragma unroll 8
        for (int k = 0; k < KP; ++k) {
            float xv0 = Xsrc[ty * NN + kp * KP + k];
            float xv1 = Xsrc[(ty + 16) * NN + kp * KP + k];
            const float4* arow = (const float4*)(As + k * NN);
#pragma unroll
            for (int c = 0; c < 4; ++c) {
                float4 a = arow[tx + 16 * c];
                acc0[4 * c + 0] += xv0 * a.x;
                acc0[4 * c + 1] += xv0 * a.y;
                acc0[4 * c + 2] += xv0 * a.z;
                acc0[4 * c + 3] += xv0 * a.w;
                acc1[4 * c + 0] += xv1 * a.x;
                acc1[4 * c + 1] += xv1 * a.y;
                acc1[4 * c + 2] += xv1 * a.z;
                acc1[4 * c + 3] += xv1 * a.w;
            }
        }
    }

    __syncthreads();   // all reads of Xsrc/Xdst done before overwrite
    float4* d4 = (float4*)Xdst;
#pragma unroll
    for (int c = 0; c < 4; ++c) {
        d4[ty * 64 + 16 * c + tx] =
            make_float4(acc0[4 * c + 0], acc0[4 * c + 1], acc0[4 * c + 2], acc0[4 * c + 3]);
        d4[(ty + 16) * 64 + 16 * c + tx] =
            make_float4(acc1[4 * c + 0], acc1[4 * c + 1], acc1[4 * c + 2], acc1[4 * c + 3]);
    }
    __syncthreads();   // Xdst visible to all
}

__device__ __forceinline__ void mix_step(
    const float* Bs,                 // smem [32][256] (channel-slice of h)
    const float* __restrict__ W,     // [64][224] global (L1/L2 resident)
    int cb,                          // channel base in concat
    float (&yacc)[4][16],
    int tx, int ty)
{
#pragma unroll 8
    for (int k = 0; k < 32; ++k) {
        float w0 = W[(ty     ) * CC + cb + k];
        float w1 = W[(ty + 16) * CC + cb + k];
        float w2 = W[(ty + 32) * CC + cb + k];
        float w3 = W[(ty + 48) * CC + cb + k];
        const float4* brow = (const float4*)(Bs + k * NN);
#pragma unroll
        for (int c = 0; c < 4; ++c) {
            float4 h = brow[tx + 16 * c];
            yacc[0][4 * c + 0] += w0 * h.x; yacc[0][4 * c + 1] += w0 * h.y;
            yacc[0][4 * c + 2] += w0 * h.z; yacc[0][4 * c + 3] += w0 * h.w;
            yacc[1][4 * c + 0] += w1 * h.x; yacc[1][4 * c + 1] += w1 * h.y;
            yacc[1][4 * c + 2] += w1 * h.z; yacc[1][4 * c + 3] += w1 * h.w;
            yacc[2][4 * c + 0] += w2 * h.x; yacc[2][4 * c + 1] += w2 * h.y;
            yacc[2][4 * c + 2] += w2 * h.z; yacc[2][4 * c + 3] += w2 * h.w;
            yacc[3][4 * c + 0] += w3 * h.x; yacc[3][4 * c + 1] += w3 * h.y;
            yacc[3][4 * c + 2] += w3 * h.z; yacc[3][4 * c + 3] += w3 * h.w;
        }
    }
}

__global__ __launch_bounds__(256)
void gcn_fused_kernel(
    const float* __restrict__ x,      // [8][32][256][64]
    const float* __restrict__ base0,  // [8][64][256][256]
    const float* __restrict__ base1,
    const float* __restrict__ base2,
    const float* __restrict__ W,      // [64][224]
    const float* __restrict__ bias,   // [64]
    float* __restrict__ y)            // [8][64][256][64]
{
    extern __shared__ float smem[];
    float* Xs  = smem;            // 8192
    float* X1s = smem + 8192;     // 8192
    float* As  = smem + 16384;    // 8192

    const int t  = threadIdx.x;
    const int tx = t & 15;
    const int ty = t >> 4;
    const int bm = blockIdx.x;    // b*64 + m
    const int b  = bm >> 6;
    const int m  = bm & 63;

    // Load X[f][n] = x[b][f][n][m]  (strided in m; one-time cost)
#pragma unroll
    for (int i = 0; i < 32; ++i) {
        int idx = t + 256 * i;            // 0..8191
        int f = idx >> 8, n = idx & 255;
        Xs[idx] = x[(((size_t)b * F_ + f) * NN + n) * MM + m];
    }
    __syncthreads();

    // Y accumulators: rows o = ty + 16r, cols v = 4*tx + 64*cc + j
    float yacc[4][16];
#pragma unroll
    for (int r = 0; r < 4; ++r) {
        float bb = bias[ty + 16 * r];
#pragma unroll
        for (int c = 0; c < 16; ++c) yacc[r][c] = bb;
    }

    // Slot 0: Y += W[:,0:32] * X
    mix_step(Xs, W, 0, yacc, tx, ty);

    const float* bases[3] = { base0, base1, base2 };
#pragma unroll 1
    for (int iB = 0; iB < 3; ++iB) {
        const float* Ag = bases[iB] + (size_t)bm * (NN * NN);

        // X1 = X * A
        nconv_step(Ag, Xs, X1s, As, tx, ty, t);
        mix_step(X1s, W, 32 + iB * 64, yacc, tx, ty);

        // X2 = X1 * A   (in place: full register accumulation before store)
        nconv_step(Ag, X1s, X1s, As, tx, ty, t);
        mix_step(X1s, W, 64 + iB * 64, yacc, tx, ty);
    }

    // Write y[b][o][v][m]
#pragma unroll
    for (int r = 0; r < 4; ++r) {
        int o = ty + 16 * r;
#pragma unroll
        for (int cc = 0; cc < 4; ++cc) {
#pragma unroll
            for (int j = 0; j < 4; ++j) {
                int v = 4 * tx + 64 * cc + j;
                y[(((size_t)b * CO + o) * NN + v) * MM + m] = yacc[r][4 * cc + j];
            }
        }
    }
}

extern "C" void kernel_launch(void* const* d_in, const int* in_sizes, int n_in,
                              void* d_out, int out_size)
{
    const float* x     = (const float*)d_in[0];
    const float* base0 = (const float*)d_in[1];
    const float* base1 = (const float*)d_in[2];
    const float* base2 = (const float*)d_in[3];
    const float* W     = (const float*)d_in[4];
    const float* bias  = (const float*)d_in[5];
    float* y = (float*)d_out;

    const int smem_bytes = 3 * 8192 * sizeof(float);  // 96 KB
    cudaFuncSetAttribute(gcn_fused_kernel,
                         cudaFuncAttributeMaxDynamicSharedMemorySize, smem_bytes);

    gcn_fused_kernel<<<B_ * MM, 256, smem_bytes>>>(x, base0, base1, base2, W, bias, y);
}

// round 6
// speedup vs baseline: 1.8394x; 1.8394x over previous
#include <cuda_runtime.h>
#include <cstdint>

// Problem constants
#define B_   8
#define F_   32      // input channels
#define NN   256     // nodes
#define MM   64
#define CO   64      // output channels
#define CC   224     // concat channels = 7*32

// 512 threads per CTA. Thread layout: tx4 = t & 63 (float4 column 0..63),
// ty4 = t >> 6 (row group 0..7).
//
// SMEM (floats):
//   Xs  [32*256]  : X tile (persistent)            8192
//   X1s [32*256]  : X1/X2 tile                     8192
//   As0 [32*256]  : A panel buffer 0               8192
//   As1 [32*256]  : A panel buffer 1               8192
// total 32768 floats = 128 KB

__device__ __forceinline__ void cp_async16(void* smem_dst, const void* gmem_src) {
    uint32_t s = (uint32_t)__cvta_generic_to_shared(smem_dst);
    asm volatile("cp.async.cg.shared.global [%0], [%1], 16;\n" :: "r"(s), "l"(gmem_src));
}
__device__ __forceinline__ void cp_commit() {
    asm volatile("cp.async.commit_group;\n");
}
template <int N>
__device__ __forceinline__ void cp_wait() {
    asm volatile("cp.async.wait_group %0;\n" :: "n"(N));
}

__device__ __forceinline__ void issue_panel_copy(float* dst, const float* src, int t) {
    const float4* s4 = (const float4*)src;
    float4* d4 = (float4*)dst;
#pragma unroll
    for (int i = 0; i < 4; ++i)           // 2048 float4 / 512 threads
        cp_async16(&d4[t + 512 * i], &s4[t + 512 * i]);
    cp_commit();
}

// X1[f][v] = sum_n X[f][n] * A[n][v];  X: [32][256] smem, A streamed in 32-row panels.
// Each thread: rows {ty4, ty4+8, ty4+16, ty4+24}, one float4 column tx4.
__device__ __forceinline__ void nconv_step(
    const float* __restrict__ Ag,    // global A[b][m]: [256][256]
    const float* Xsrc, float* Xdst,  // smem [32][256] (may alias)
    float* As0, float* As1,
    int t, int tx4, int ty4)
{
    float acc[4][4];
#pragma unroll
    for (int r = 0; r < 4; ++r)
#pragma unroll
        for (int c = 0; c < 4; ++c) acc[r][c] = 0.f;

    float* bufs[2] = { As0, As1 };
    issue_panel_copy(As0, Ag, t);                       // group for panel 0

#pragma unroll 1
    for (int kp = 0; kp < 8; ++kp) {
        if (kp < 7) {
            issue_panel_copy(bufs[(kp + 1) & 1], Ag + (kp + 1) * 8192, t);
            cp_wait<1>();          // panel kp arrived (mine)
        } else {
            cp_wait<0>();
        }
        __syncthreads();           // panel kp visible to all

        const float* As = bufs[kp & 1];
#pragma unroll
        for (int kk = 0; kk < 8; ++kk) {
            float4 xv[4];
#pragma unroll
            for (int r = 0; r < 4; ++r)
                xv[r] = *(const float4*)&Xsrc[(ty4 + 8 * r) * NN + kp * 32 + kk * 4];
#pragma unroll
            for (int j = 0; j < 4; ++j) {
                float4 a = *(const float4*)&As[(kk * 4 + j) * NN + tx4 * 4];
#pragma unroll
                for (int r = 0; r < 4; ++r) {
                    float xs = (j == 0) ? xv[r].x : (j == 1) ? xv[r].y
                             : (j == 2) ? xv[r].z : xv[r].w;
                    acc[r][0] += xs * a.x;
                    acc[r][1] += xs * a.y;
                    acc[r][2] += xs * a.z;
                    acc[r][3] += xs * a.w;
                }
            }
        }
        __syncthreads();           // all reads of panel kp done (buffer reused at kp+2)
    }

    // All compute (including reads of Xsrc) finished at the last barrier.
#pragma unroll
    for (int r = 0; r < 4; ++r)
        *(float4*)&Xdst[(ty4 + 8 * r) * NN + tx4 * 4] =
            make_float4(acc[r][0], acc[r][1], acc[r][2], acc[r][3]);
    __syncthreads();               // Xdst visible
}

// Y[o][v] += sum_k W[o][cb+k] * Bs[k][v], k in [0,32)
// Each thread: rows {ty4 + 8r : r<8}, one float4 column tx4.
__device__ __forceinline__ void mix_step(
    const float* Bs,                 // smem [32][256]
    const float* __restrict__ W,     // [64][224] global (L1-resident)
    int cb,
    float (&yacc)[8][4],
    int tx4, int ty4)
{
#pragma unroll
    for (int kk = 0; kk < 8; ++kk) {
        float4 wv[8];
#pragma unroll
        for (int r = 0; r < 8; ++r)
            wv[r] = *(const float4*)&W[(ty4 + 8 * r) * CC + cb + kk * 4];
#pragma unroll
        for (int j = 0; j < 4; ++j) {
            float4 h = *(const float4*)&Bs[(kk * 4 + j) * NN + tx4 * 4];
#pragma unroll
            for (int r = 0; r < 8; ++r) {
                float ws = (j == 0) ? wv[r].x : (j == 1) ? wv[r].y
                         : (j == 2) ? wv[r].z : wv[r].w;
                yacc[r][0] += ws * h.x;
                yacc[r][1] += ws * h.y;
                yacc[r][2] += ws * h.z;
                yacc[r][3] += ws * h.w;
            }
        }
    }
}

__global__ __launch_bounds__(512, 1)
void gcn_fused_kernel(
    const float* __restrict__ x,      // [8][32][256][64]
    const float* __restrict__ base0,  // [8][64][256][256]
    const float* __restrict__ base1,
    const float* __restrict__ base2,
    const float* __restrict__ W,      // [64][224]
    const float* __restrict__ bias,   // [64]
    float* __restrict__ y)            // [8][64][256][64]
{
    extern __shared__ float smem[];
    float* Xs  = smem;             // 8192
    float* X1s = smem + 8192;      // 8192
    float* As0 = smem + 16384;     // 8192
    float* As1 = smem + 24576;     // 8192

    const int t   = threadIdx.x;
    const int tx4 = t & 63;
    const int ty4 = t >> 6;
    const int bm  = blockIdx.x;    // b*64 + m
    const int b   = bm >> 6;
    const int m   = bm & 63;

    // Load X[f][n] = x[b][f][n][m]
#pragma unroll
    for (int i = 0; i < 16; ++i) {
        int idx = t + 512 * i;             // 0..8191
        int f = idx >> 8, n = idx & 255;
        Xs[idx] = x[(((size_t)b * F_ + f) * NN + n) * MM + m];
    }
    __syncthreads();

    float yacc[8][4];
#pragma unroll
    for (int r = 0; r < 8; ++r) {
        float bb = bias[ty4 + 8 * r];
#pragma unroll
        for (int c = 0; c < 4; ++c) yacc[r][c] = bb;
    }

    // slot 0: Y += W[:,0:32] * X
    mix_step(Xs, W, 0, yacc, tx4, ty4);

    const float* bases[3] = { base0, base1, base2 };
#pragma unroll 1
    for (int iB = 0; iB < 3; ++iB) {
        const float* Ag = bases[iB] + (size_t)bm * (NN * NN);

        nconv_step(Ag, Xs, X1s, As0, As1, t, tx4, ty4);
        mix_step(X1s, W, 32 + iB * 64, yacc, tx4, ty4);

        nconv_step(Ag, X1s, X1s, As0, As1, t, tx4, ty4);   // in-place: reg-accumulated
        mix_step(X1s, W, 64 + iB * 64, yacc, tx4, ty4);
    }

    // Store y[b][o][v][m]
#pragma unroll
    for (int r = 0; r < 8; ++r) {
        int o = ty4 + 8 * r;
#pragma unroll
        for (int j = 0; j < 4; ++j) {
            int v = tx4 * 4 + j;
            y[(((size_t)b * CO + o) * NN + v) * MM + m] = yacc[r][j];
        }
    }
}

extern "C" void kernel_launch(void* const* d_in, const int* in_sizes, int n_in,
                              void* d_out, int out_size)
{
    const float* x     = (const float*)d_in[0];
    const float* base0 = (const float*)d_in[1];
    const float* base1 = (const float*)d_in[2];
    const float* base2 = (const float*)d_in[3];
    const float* W     = (const float*)d_in[4];
    const float* bias  = (const float*)d_in[5];
    float* y = (float*)d_out;

    const int smem_bytes = 4 * 8192 * sizeof(float);  // 128 KB
    cudaFuncSetAttribute(gcn_fused_kernel,
                         cudaFuncAttributeMaxDynamicSharedMemorySize, smem_bytes);

    gcn_fused_kernel<<<B_ * MM, 512, smem_bytes>>>(x, base0, base1, base2, W, bias, y);
}